// round 2
// baseline (speedup 1.0000x reference)
#include <cuda_runtime.h>

// Help_36567351558250: fused 3DGS covariance-axes kernel. R2:
//  - 2 rows per thread (MLP ~16) to saturate HBM under DRAM latency
//  - __ldcs / __stcs streaming hints (zero-reuse stream, evict-first)
//  - float4 writeback from SMEM (STG.128, fewer L1 wavefronts)

#define TPB 256
#define RPT 2               // rows per thread
#define RPB (TPB * RPT)     // 512 rows per block

__device__ __forceinline__ void compute_row(
    const float4 q, const float2 sc, const float4 c0, const float4 c1,
    const float4 c2, const float4 c3, const float p0, const float p1,
    const float p2, const float m, float* __restrict__ s /* 9 floats */)
{
    const float r = q.x, x = q.y, y = q.z, z = q.w;
    const float R00 = 1.0f - 2.0f * (y * y + z * z);
    const float R10 = 2.0f * (x * y + r * z);
    const float R20 = 2.0f * (x * z - r * y);
    const float R01 = 2.0f * (x * y - r * z);
    const float R11 = 1.0f - 2.0f * (x * x + z * z);
    const float R21 = 2.0f * (y * z + r * x);

    const float s0 = m * sc.x;
    const float s1 = m * sc.y;
    const float u0 = s0 * R00, u1 = s0 * R10, u2 = s0 * R20;
    const float v0 = s1 * R01, v1 = s1 * R11, v2 = s1 * R21;

    s[0] = c0.x * u0 + c1.x * u1 + c2.x * u2;
    s[1] = c0.x * v0 + c1.x * v1 + c2.x * v2;
    s[2] = c0.x * p0 + c1.x * p1 + c2.x * p2 + c3.x;
    s[3] = c0.y * u0 + c1.y * u1 + c2.y * u2;
    s[4] = c0.y * v0 + c1.y * v1 + c2.y * v2;
    s[5] = c0.y * p0 + c1.y * p1 + c2.y * p2 + c3.y;
    s[6] = c0.z * u0 + c1.z * u1 + c2.z * u2;
    s[7] = c0.z * v0 + c1.z * v1 + c2.z * v2;
    s[8] = c0.z * p0 + c1.z * p1 + c2.z * p2 + c3.z;
}

__global__ __launch_bounds__(TPB) void gs_cov_kernel(
    const float4* __restrict__ rot,      // N x 4
    const float*  __restrict__ mod,      // 1
    const float2* __restrict__ scale,    // N x 2
    const float*  __restrict__ p_k,      // N x 3
    const float4* __restrict__ vm4,      // N x 16 viewed as N*4 float4
    float*        __restrict__ out,      // N x 9
    int N)
{
    __shared__ float sbuf[RPB * 9];      // 18432 B

    const int t  = threadIdx.x;
    const float m = __ldg(mod);

    const int r0 = blockIdx.x * RPB + t;         // first row
    const int r1 = r0 + TPB;                     // second row (coalesced)

    // ---- front-batched streaming loads for both rows (MLP ~16) ----
    if (r0 < N) {
        const float4 q  = __ldcs(&rot[r0]);
        const float2 sc = __ldcs(&scale[r0]);
        const float4 c0 = __ldcs(&vm4[r0 * 4 + 0]);
        const float4 c1 = __ldcs(&vm4[r0 * 4 + 1]);
        const float4 c2 = __ldcs(&vm4[r0 * 4 + 2]);
        const float4 c3 = __ldcs(&vm4[r0 * 4 + 3]);
        const float  p0 = __ldcs(&p_k[r0 * 3 + 0]);
        const float  p1 = __ldcs(&p_k[r0 * 3 + 1]);
        const float  p2 = __ldcs(&p_k[r0 * 3 + 2]);
        compute_row(q, sc, c0, c1, c2, c3, p0, p1, p2, m, &sbuf[t * 9]);
    }
    if (r1 < N) {
        const float4 q  = __ldcs(&rot[r1]);
        const float2 sc = __ldcs(&scale[r1]);
        const float4 c0 = __ldcs(&vm4[r1 * 4 + 0]);
        const float4 c1 = __ldcs(&vm4[r1 * 4 + 1]);
        const float4 c2 = __ldcs(&vm4[r1 * 4 + 2]);
        const float4 c3 = __ldcs(&vm4[r1 * 4 + 3]);
        const float  p0 = __ldcs(&p_k[r1 * 3 + 0]);
        const float  p1 = __ldcs(&p_k[r1 * 3 + 1]);
        const float  p2 = __ldcs(&p_k[r1 * 3 + 2]);
        compute_row(q, sc, c0, c1, c2, c3, p0, p1, p2, m, &sbuf[(TPB + t) * 9]);
    }
    __syncthreads();

    // ---- coalesced float4 writeback: block region is a contiguous prefix ----
    const float4* s4     = (const float4*)sbuf;
    float4*       out4   = (float4*)out;
    const long    base4  = (long)blockIdx.x * (RPB * 9 / 4);   // 1152 float4/block
    const long    nOut4  = (long)N * 9 / 4;                    // N*9 divisible by 4 here? guard anyway

    #pragma unroll
    for (int i = 0; i < RPB * 9 / 4; i += TPB) {
        const int  li = i + t;
        const long gi = base4 + li;
        if (li < RPB * 9 / 4 && gi < nOut4) __stcs(&out4[gi], s4[li]);
    }

    // tail floats if N*9 % 4 != 0 (not the case for N=2e6, but stay correct)
    const long nOut = (long)N * 9;
    const long done = nOut4 * 4;
    if (blockIdx.x == gridDim.x - 1) {
        for (long gi = done + t; gi < nOut; gi += TPB) {
            const long li = gi - (long)blockIdx.x * (RPB * 9);
            if (li >= 0 && li < RPB * 9) out[gi] = sbuf[li];
        }
    }
}

extern "C" void kernel_launch(void* const* d_in, const int* in_sizes, int n_in,
                              void* d_out, int out_size) {
    const float4* rot   = (const float4*)d_in[0];
    const float*  mod   = (const float*)d_in[1];
    const float2* scale = (const float2*)d_in[2];
    const float*  p_k   = (const float*)d_in[3];
    const float4* vm4   = (const float4*)d_in[4];
    float*        out   = (float*)d_out;

    const int N = in_sizes[0] / 4;   // rot has N*4 elements
    const int blocks = (N + RPB - 1) / RPB;
    gs_cov_kernel<<<blocks, TPB>>>(rot, mod, scale, p_k, vm4, out, N);
}